// round 7
// baseline (speedup 1.0000x reference)
#include <cuda_runtime.h>

// Problem constants
#define XD      40      // X_DIM
#define ROWS    8       // batch rows per block
#define NTHREADS (ROWS * XD)   // 320
#define C1      72      // conv1 out channels
#define CH      48      // gated channels (conv2 in)
#define CO      37      // conv2 out channels
#define W2_STRIDE 40    // padded co stride for 16B-aligned packed loads

// Dynamic smem layout (floats):
//  W2s   : CH*5*W2_STRIDE = 9600   ([ci][k][co] transposed, padded)
//  Hs    : ROWS*CH*XD     = 15360
//  W1s   : C1*5           = 360
//  b1s   : C1             = 72
//  b2s   : CO+3           = 40   (padded so following arrays stay aligned)
//  W3s   : CO             = 37
//  cfs   : 18
//  us    : ROWS*XD        = 320
#define SMEM_FLOATS (9600 + 15360 + 360 + 72 + 40 + 37 + 18 + 320 + 1)
#define SMEM_BYTES  (SMEM_FLOATS * 4)

__global__ void __launch_bounds__(NTHREADS, 2)
lorenz96_corr_kernel(const float* __restrict__ u,
                     const float* __restrict__ coeff,
                     const float* __restrict__ W1,
                     const float* __restrict__ b1,
                     const float* __restrict__ W2,
                     const float* __restrict__ b2,
                     const float* __restrict__ W3,
                     const float* __restrict__ b3,
                     float* __restrict__ out)
{
    extern __shared__ float smem[];
    float* W2s = smem;                      // 9600
    float* Hs  = W2s + CH * 5 * W2_STRIDE;  // 15360
    float* W1s = Hs + ROWS * CH * XD;       // 360
    float* b1s = W1s + C1 * 5;              // 72
    float* b2s = b1s + C1;                  // 40 (37 used) -- 8B aligned
    float* W3s = b2s + 40;                  // 37
    float* cfs = W3s + CO;                  // 18
    float* us  = cfs + 18;                  // 320

    const int tid = threadIdx.x;
    const long base = (long)blockIdx.x * ROWS * XD;

    // ---- cooperative loads ----
    // W2 global layout: [co][ci][k] (co*240 + ci*5 + k). Store as [ci*5+k][co] padded.
    for (int i = tid; i < CO * CH * 5; i += NTHREADS) {
        int co = i / (CH * 5);
        int r  = i % (CH * 5);          // r = ci*5 + k
        W2s[r * W2_STRIDE + co] = W2[i];
    }
    for (int i = tid; i < C1 * 5; i += NTHREADS) W1s[i] = W1[i];
    if (tid < C1) b1s[tid] = b1[tid];
    if (tid < CO) { b2s[tid] = b2[tid]; W3s[tid] = W3[tid]; }
    if (tid < 18) cfs[tid] = coeff[tid];
    us[tid] = u[base + tid];
    __syncthreads();

    const int r = tid / XD;
    const int p = tid % XD;
    const int im2 = (p + XD - 2) % XD;
    const int im1 = (p + XD - 1) % XD;
    const int ip1 = (p + 1) % XD;
    const int ip2 = (p + 2) % XD;

    const float* ur = us + r * XD;
    const float u0 = ur[im2], u1 = ur[im1], u2 = ur[p], u3 = ur[ip1], u4 = ur[ip2];

    // ---- Phase A: conv1 (circular, k=5) + ReLU + gating -> Hs[r][ci][p] ----
    float* Hrow = Hs + r * CH * XD;
    #pragma unroll 4
    for (int c = 0; c < 24; c++) {
        const float* w = &W1s[c * 5];
        float s = b1s[c];
        s = fmaf(w[0], u0, s); s = fmaf(w[1], u1, s); s = fmaf(w[2], u2, s);
        s = fmaf(w[3], u3, s); s = fmaf(w[4], u4, s);
        Hrow[c * XD + p] = fmaxf(s, 0.0f);
    }
    #pragma unroll 4
    for (int j = 0; j < 24; j++) {
        const float* wa = &W1s[(24 + j) * 5];
        const float* wb = &W1s[(48 + j) * 5];
        float sa = b1s[24 + j];
        sa = fmaf(wa[0], u0, sa); sa = fmaf(wa[1], u1, sa); sa = fmaf(wa[2], u2, sa);
        sa = fmaf(wa[3], u3, sa); sa = fmaf(wa[4], u4, sa);
        float sb = b1s[48 + j];
        sb = fmaf(wb[0], u0, sb); sb = fmaf(wb[1], u1, sb); sb = fmaf(wb[2], u2, sb);
        sb = fmaf(wb[3], u3, sb); sb = fmaf(wb[4], u4, sb);
        Hrow[(24 + j) * XD + p] = fmaxf(sa, 0.0f) * fmaxf(sb, 0.0f);
    }
    __syncthreads();

    // ---- out1: polynomial features . coeff ----
    float o1 = cfs[0];
    o1 = fmaf(cfs[1], u0, o1);  o1 = fmaf(cfs[2], u1, o1);
    o1 = fmaf(cfs[3], u2, o1);  o1 = fmaf(cfs[4], u3, o1);
    o1 = fmaf(cfs[5], u4, o1);
    o1 = fmaf(cfs[6],  u0 * u0, o1); o1 = fmaf(cfs[7],  u1 * u1, o1);
    o1 = fmaf(cfs[8],  u2 * u2, o1); o1 = fmaf(cfs[9],  u3 * u3, o1);
    o1 = fmaf(cfs[10], u4 * u4, o1);
    o1 = fmaf(cfs[11], u0 * u1, o1); o1 = fmaf(cfs[12], u1 * u2, o1);
    o1 = fmaf(cfs[13], u2 * u3, o1); o1 = fmaf(cfs[14], u3 * u4, o1);
    o1 = fmaf(cfs[15], u0 * u2, o1); o1 = fmaf(cfs[16], u1 * u3, o1);
    o1 = fmaf(cfs[17], u2 * u4, o1);

    // ---- Phase B: conv2 (circular) + ReLU + conv3 fused, packed f32x2 FMA ----
    // 36 accumulators as 18 x f32x2 pairs + 1 scalar (co=36).
    unsigned long long accp[18];
    {
        const unsigned long long* b2p =
            reinterpret_cast<const unsigned long long*>(b2s);
        #pragma unroll
        for (int q = 0; q < 18; q++) accp[q] = b2p[q];
    }
    float acc36 = b2s[36];

    #pragma unroll 1
    for (int ci = 0; ci < CH; ci++) {
        const float* hc = Hrow + ci * XD;
        float hv[5];
        hv[0] = hc[im2]; hv[1] = hc[im1]; hv[2] = hc[p];
        hv[3] = hc[ip1]; hv[4] = hc[ip2];
        const float* wbase = W2s + ci * 5 * W2_STRIDE;
        #pragma unroll
        for (int k = 0; k < 5; k++) {
            const float hvk = hv[k];
            unsigned long long hp;
            asm("mov.b64 %0, {%1, %1};" : "=l"(hp) : "f"(hvk));
            const ulonglong2* wrow =
                reinterpret_cast<const ulonglong2*>(wbase + k * W2_STRIDE);
            #pragma unroll
            for (int q = 0; q < 9; q++) {
                ulonglong2 wv = wrow[q];   // 4 floats = 2 f32x2 pairs (LDS.128)
                asm("fma.rn.f32x2 %0, %1, %2, %0;"
                    : "+l"(accp[2 * q])     : "l"(hp), "l"(wv.x));
                asm("fma.rn.f32x2 %0, %1, %2, %0;"
                    : "+l"(accp[2 * q + 1]) : "l"(hp), "l"(wv.y));
            }
            acc36 = fmaf(hvk, (wbase + k * W2_STRIDE)[36], acc36);
        }
    }

    // ---- epilogue: ReLU + conv3 (1x1 over 37 channels) ----
    float o2 = b3[0];
    #pragma unroll
    for (int q = 0; q < 18; q++) {
        float lo, hi;
        asm("mov.b64 {%0, %1}, %2;" : "=f"(lo), "=f"(hi) : "l"(accp[q]));
        o2 = fmaf(W3s[2 * q],     fmaxf(lo, 0.0f), o2);
        o2 = fmaf(W3s[2 * q + 1], fmaxf(hi, 0.0f), o2);
    }
    o2 = fmaf(W3s[36], fmaxf(acc36, 0.0f), o2);

    out[base + tid] = o1 + o2;
}

extern "C" void kernel_launch(void* const* d_in, const int* in_sizes, int n_in,
                              void* d_out, int out_size)
{
    // metadata order: t, u, coeff, W1, b1, W2, b2, W3, b3
    const float* u     = (const float*)d_in[1];
    const float* coeff = (const float*)d_in[2];
    const float* W1    = (const float*)d_in[3];
    const float* b1    = (const float*)d_in[4];
    const float* W2    = (const float*)d_in[5];
    const float* b2    = (const float*)d_in[6];
    const float* W3    = (const float*)d_in[7];
    const float* b3    = (const float*)d_in[8];
    float* out = (float*)d_out;

    const int n_rows = in_sizes[1] / XD;         // 65536
    const int grid = n_rows / ROWS;              // 8192

    // Idempotent host-side attribute set (not a captured stream op).
    cudaFuncSetAttribute(lorenz96_corr_kernel,
                         cudaFuncAttributeMaxDynamicSharedMemorySize, SMEM_BYTES);

    lorenz96_corr_kernel<<<grid, NTHREADS, SMEM_BYTES>>>(
        u, coeff, W1, b1, W2, b2, W3, b3, out);
}

// round 12
// speedup vs baseline: 1.0133x; 1.0133x over previous
#include <cuda_runtime.h>

typedef unsigned long long ull;

#define XD      40
#define ROWS    8
#define GROUPS  10           // 40 / P
#define P       4            // positions per thread
#define NT      (ROWS * GROUPS * 2)   // 160 threads (S=2 co-split)
#define C1      72
#define CH      48
#define CO      37
#define COP     40           // padded co stride
#define HS_RSTRIDE (CH * XD + 8)   // 1928: pad to spread banks across rows

// smem (floats): W2s 9600 | Hs 8*1928=15424 | W1s 360 | b1s 72 | b2s 40 | W3s 40 | cfs 18 | us 320
#define SMEM_FLOATS (CH*5*COP + ROWS*HS_RSTRIDE + C1*5 + C1 + COP + COP + 18 + ROWS*XD)
#define SMEM_BYTES  (SMEM_FLOATS * 4)

__global__ void __launch_bounds__(NT, 2)
lorenz96_corr_kernel(const float* __restrict__ u,
                     const float* __restrict__ coeff,
                     const float* __restrict__ W1,
                     const float* __restrict__ b1,
                     const float* __restrict__ W2,
                     const float* __restrict__ b2,
                     const float* __restrict__ W3,
                     const float* __restrict__ b3,
                     float* __restrict__ out)
{
    extern __shared__ float smem[];
    float* W2s = smem;                        // [cik 240][co 40 pad]
    float* Hs  = W2s + CH * 5 * COP;          // [r][ci][40], row stride 1928
    float* W1s = Hs + ROWS * HS_RSTRIDE;
    float* b1s = W1s + C1 * 5;
    float* b2s = b1s + C1;                    // 40 (pad zeros) -- 16B aligned
    float* W3s = b2s + COP;                   // 40 (pad zeros)
    float* cfs = W3s + COP;
    float* us  = cfs + 18;                    // [r][40]

    const int tid = threadIdx.x;
    const long base = (long)blockIdx.x * ROWS * XD;

    // ---- cooperative loads ----
    // W2 global [co][ci][k] -> W2s[(ci*5+k)*40 + co], zero-pad co 37..39
    for (int i = tid; i < CH * 5 * COP; i += NT) {
        int cik = i / COP;
        int co  = i % COP;
        W2s[i] = (co < CO) ? W2[co * (CH * 5) + cik] : 0.0f;
    }
    for (int i = tid; i < C1 * 5; i += NT) W1s[i] = W1[i];
    if (tid < C1) b1s[tid] = b1[tid];
    if (tid < COP) {
        b2s[tid] = (tid < CO) ? b2[tid] : 0.0f;
        W3s[tid] = (tid < CO) ? W3[tid] : 0.0f;
    }
    if (tid < 18) cfs[tid] = coeff[tid];
    for (int i = tid; i < ROWS * XD; i += NT) us[i] = u[base + i];
    __syncthreads();

    // ---- Phase A: conv1 + ReLU + gating, 2 position-columns per thread ----
    for (int col = tid; col < ROWS * XD; col += NT) {
        const int rr = col / XD;
        const int pp = col % XD;
        const int am2 = (pp + XD - 2) % XD, am1 = (pp + XD - 1) % XD;
        const int ap1 = (pp + 1) % XD,      ap2 = (pp + 2) % XD;
        const float* ur = us + rr * XD;
        const float v0 = ur[am2], v1 = ur[am1], v2 = ur[pp], v3 = ur[ap1], v4 = ur[ap2];
        float* Hr = Hs + rr * HS_RSTRIDE;
        #pragma unroll 4
        for (int c = 0; c < 24; c++) {
            const float* w = &W1s[c * 5];
            float sacc = b1s[c];
            sacc = fmaf(w[0], v0, sacc); sacc = fmaf(w[1], v1, sacc);
            sacc = fmaf(w[2], v2, sacc); sacc = fmaf(w[3], v3, sacc);
            sacc = fmaf(w[4], v4, sacc);
            Hr[c * XD + pp] = fmaxf(sacc, 0.0f);
        }
        #pragma unroll 4
        for (int j = 0; j < 24; j++) {
            const float* wa = &W1s[(24 + j) * 5];
            const float* wb = &W1s[(48 + j) * 5];
            float sa = b1s[24 + j];
            sa = fmaf(wa[0], v0, sa); sa = fmaf(wa[1], v1, sa); sa = fmaf(wa[2], v2, sa);
            sa = fmaf(wa[3], v3, sa); sa = fmaf(wa[4], v4, sa);
            float sb = b1s[48 + j];
            sb = fmaf(wb[0], v0, sb); sb = fmaf(wb[1], v1, sb); sb = fmaf(wb[2], v2, sb);
            sb = fmaf(wb[3], v3, sb); sb = fmaf(wb[4], v4, sb);
            Hr[(24 + j) * XD + pp] = fmaxf(sa, 0.0f) * fmaxf(sb, 0.0f);
        }
    }
    __syncthreads();

    // ---- Phase B: thread = (row r, pos-group g of 4, co-half s) ----
    const int s  = tid & 1;
    const int g  = (tid >> 1) % GROUPS;
    const int r  = tid / (GROUPS * 2);
    const int pbase = g * P;
    const int co0 = s * 20;

    int hidx[8];
    #pragma unroll
    for (int j = 0; j < 8; j++) hidx[j] = (pbase + XD - 2 + j) % XD;

    // 4 pos x 10 co-pairs accumulators
    ull accp[P * 10];
    {
        const ull* bp = reinterpret_cast<const ull*>(b2s + co0);
        #pragma unroll
        for (int j2 = 0; j2 < P; j2++)
            #pragma unroll
            for (int q = 0; q < 10; q++) accp[j2 * 10 + q] = bp[q];
    }

    const float* HrowR = Hs + r * HS_RSTRIDE;
    #pragma unroll 1
    for (int ci = 0; ci < CH; ci++) {
        const float* hc = HrowR + ci * XD;
        ull hp[8];
        #pragma unroll
        for (int j = 0; j < 8; j++) {
            float hv = hc[hidx[j]];
            asm("mov.b64 %0, {%1, %1};" : "=l"(hp[j]) : "f"(hv));
        }
        const float* wb = W2s + ci * 5 * COP + co0;
        #pragma unroll
        for (int k = 0; k < 5; k++) {
            const ulonglong2* wv = reinterpret_cast<const ulonglong2*>(wb + k * COP);
            ulonglong2 a0 = wv[0], a1 = wv[1], a2 = wv[2], a3 = wv[3], a4 = wv[4];
            ull wp[10] = {a0.x, a0.y, a1.x, a1.y, a2.x, a2.y, a3.x, a3.y, a4.x, a4.y};
            #pragma unroll
            for (int j2 = 0; j2 < P; j2++) {
                const ull h2 = hp[j2 + k];
                #pragma unroll
                for (int q = 0; q < 10; q++) {
                    asm("fma.rn.f32x2 %0, %1, %2, %0;"
                        : "+l"(accp[j2 * 10 + q]) : "l"(h2), "l"(wp[q]));
                }
            }
        }
    }

    // ---- epilogue: ReLU + conv3 partial dot over this thread's 20 co ----
    float o2p[P];
    #pragma unroll
    for (int j2 = 0; j2 < P; j2++) {
        float a2 = 0.0f;
        #pragma unroll
        for (int q = 0; q < 10; q++) {
            float lo, hi;
            asm("mov.b64 {%0, %1}, %2;" : "=f"(lo), "=f"(hi) : "l"(accp[j2 * 10 + q]));
            a2 = fmaf(W3s[co0 + 2 * q],     fmaxf(lo, 0.0f), a2);
            a2 = fmaf(W3s[co0 + 2 * q + 1], fmaxf(hi, 0.0f), a2);
        }
        o2p[j2] = a2;
    }
    // combine the two co-halves (lanes s and s^1 are warp-adjacent)
    float o2t[P];
    #pragma unroll
    for (int j2 = 0; j2 < P; j2++)
        o2t[j2] = o2p[j2] + __shfl_xor_sync(0xffffffffu, o2p[j2], 1);

    if (s == 0) {
        const float* ur = us + r * XD;
        float uw[8];
        #pragma unroll
        for (int j = 0; j < 8; j++) uw[j] = ur[hidx[j]];
        const float bb3 = b3[0];
        float res[P];
        #pragma unroll
        for (int j2 = 0; j2 < P; j2++) {
            const float v0 = uw[j2], v1 = uw[j2 + 1], v2 = uw[j2 + 2],
                        v3 = uw[j2 + 3], v4 = uw[j2 + 4];
            float o1 = cfs[0];
            o1 = fmaf(cfs[1], v0, o1);  o1 = fmaf(cfs[2], v1, o1);
            o1 = fmaf(cfs[3], v2, o1);  o1 = fmaf(cfs[4], v3, o1);
            o1 = fmaf(cfs[5], v4, o1);
            o1 = fmaf(cfs[6],  v0 * v0, o1); o1 = fmaf(cfs[7],  v1 * v1, o1);
            o1 = fmaf(cfs[8],  v2 * v2, o1); o1 = fmaf(cfs[9],  v3 * v3, o1);
            o1 = fmaf(cfs[10], v4 * v4, o1);
            o1 = fmaf(cfs[11], v0 * v1, o1); o1 = fmaf(cfs[12], v1 * v2, o1);
            o1 = fmaf(cfs[13], v2 * v3, o1); o1 = fmaf(cfs[14], v3 * v4, o1);
            o1 = fmaf(cfs[15], v0 * v2, o1); o1 = fmaf(cfs[16], v1 * v3, o1);
            o1 = fmaf(cfs[17], v2 * v4, o1);
            res[j2] = o1 + o2t[j2] + bb3;
        }
        float4 vres = make_float4(res[0], res[1], res[2], res[3]);
        *reinterpret_cast<float4*>(out + base + r * XD + pbase) = vres;
    }
}

extern "C" void kernel_launch(void* const* d_in, const int* in_sizes, int n_in,
                              void* d_out, int out_size)
{
    // metadata order: t, u, coeff, W1, b1, W2, b2, W3, b3
    const float* u     = (const float*)d_in[1];
    const float* coeff = (const float*)d_in[2];
    const float* W1    = (const float*)d_in[3];
    const float* b1    = (const float*)d_in[4];
    const float* W2    = (const float*)d_in[5];
    const float* b2    = (const float*)d_in[6];
    const float* W3    = (const float*)d_in[7];
    const float* b3    = (const float*)d_in[8];
    float* out = (float*)d_out;

    const int n_rows = in_sizes[1] / XD;         // 65536
    const int grid = n_rows / ROWS;              // 8192

    cudaFuncSetAttribute(lorenz96_corr_kernel,
                         cudaFuncAttributeMaxDynamicSharedMemorySize, SMEM_BYTES);

    lorenz96_corr_kernel<<<grid, NT, SMEM_BYTES>>>(
        u, coeff, W1, b1, W2, b2, W3, b3, out);
}

// round 13
// speedup vs baseline: 1.2581x; 1.2415x over previous
#include <cuda_runtime.h>

typedef unsigned long long ull;

#define XD      40
#define ROWS    8
#define GROUPS  10           // 40 / P
#define P       4            // positions per thread
#define NT      (ROWS * GROUPS * 2)   // 160 threads (S=2 co-split)
#define C1      72
#define CH      48
#define CIC     24           // ci chunk size (2 chunks)
#define CO      37
#define COP     40           // padded co stride
#define HS_RSTRIDE (CIC * XD + 8)  // 968: 24-channel chunk + pad

// smem (floats): W2s 9600 | Hs 8*968=7744 | W1s 360 | b1s 72 | b2s 40 | W3s 40 | cfs 18 | us 320
#define SMEM_FLOATS (CH*5*COP + ROWS*HS_RSTRIDE + C1*5 + C1 + COP + COP + 18 + ROWS*XD)
#define SMEM_BYTES  (SMEM_FLOATS * 4)

__global__ void __launch_bounds__(NT, 3)
lorenz96_corr_kernel(const float* __restrict__ u,
                     const float* __restrict__ coeff,
                     const float* __restrict__ W1,
                     const float* __restrict__ b1,
                     const float* __restrict__ W2,
                     const float* __restrict__ b2,
                     const float* __restrict__ W3,
                     const float* __restrict__ b3,
                     float* __restrict__ out)
{
    extern __shared__ float smem[];
    float* W2s = smem;                        // [cik 240][co 40 pad]
    float* Hs  = W2s + CH * 5 * COP;          // [r][24ci][40], row stride 968
    float* W1s = Hs + ROWS * HS_RSTRIDE;
    float* b1s = W1s + C1 * 5;
    float* b2s = b1s + C1;                    // 40 (pad zeros) -- 8B/16B aligned
    float* W3s = b2s + COP;                   // 40 (pad zeros)
    float* cfs = W3s + COP;
    float* us  = cfs + 18;                    // [r][40]

    const int tid = threadIdx.x;
    const long base = (long)blockIdx.x * ROWS * XD;

    // ---- cooperative loads ----
    // W2 global [co][ci][k] -> W2s[(ci*5+k)*40 + co], zero-pad co 37..39
    for (int i = tid; i < CH * 5 * COP; i += NT) {
        int cik = i / COP;
        int co  = i % COP;
        W2s[i] = (co < CO) ? W2[co * (CH * 5) + cik] : 0.0f;
    }
    for (int i = tid; i < C1 * 5; i += NT) W1s[i] = W1[i];
    if (tid < C1) b1s[tid] = b1[tid];
    if (tid < COP) {
        b2s[tid] = (tid < CO) ? b2[tid] : 0.0f;
        W3s[tid] = (tid < CO) ? W3[tid] : 0.0f;
    }
    if (tid < 18) cfs[tid] = coeff[tid];
    for (int i = tid; i < ROWS * XD; i += NT) us[i] = u[base + i];
    __syncthreads();

    // ---- Phase B thread mapping: (row r, pos-group g of 4, co-half s) ----
    const int s  = tid & 1;
    const int g  = (tid >> 1) % GROUPS;
    const int r  = tid / (GROUPS * 2);
    const int pbase = g * P;
    const int co0 = s * 20;

    int hidx[8];
    #pragma unroll
    for (int j = 0; j < 8; j++) hidx[j] = (pbase + XD - 2 + j) % XD;

    // 4 pos x 10 co-pairs accumulators
    ull accp[P * 10];
    {
        const ull* bp = reinterpret_cast<const ull*>(b2s + co0);
        #pragma unroll
        for (int j2 = 0; j2 < P; j2++)
            #pragma unroll
            for (int q = 0; q < 10; q++) accp[j2 * 10 + q] = bp[q];
    }

    // ---- two ci chunks: build Hs for 24 channels, consume, repeat ----
    #pragma unroll 1
    for (int chunk = 0; chunk < 2; chunk++) {
        __syncthreads();   // previous chunk's Hs fully consumed

        // Phase A for this chunk: 2 position-columns per thread
        for (int col = tid; col < ROWS * XD; col += NT) {
            const int rr = col / XD;
            const int pp = col % XD;
            const int am2 = (pp + XD - 2) % XD, am1 = (pp + XD - 1) % XD;
            const int ap1 = (pp + 1) % XD,      ap2 = (pp + 2) % XD;
            const float* ur = us + rr * XD;
            const float v0 = ur[am2], v1 = ur[am1], v2 = ur[pp],
                        v3 = ur[ap1], v4 = ur[ap2];
            float* Hr = Hs + rr * HS_RSTRIDE;
            if (chunk == 0) {
                // channels 0..23: direct ReLU conv
                #pragma unroll 4
                for (int c = 0; c < CIC; c++) {
                    const float* w = &W1s[c * 5];
                    float sacc = b1s[c];
                    sacc = fmaf(w[0], v0, sacc); sacc = fmaf(w[1], v1, sacc);
                    sacc = fmaf(w[2], v2, sacc); sacc = fmaf(w[3], v3, sacc);
                    sacc = fmaf(w[4], v4, sacc);
                    Hr[c * XD + pp] = fmaxf(sacc, 0.0f);
                }
            } else {
                // channels 24..47: relu(conv 24+j) * relu(conv 48+j)
                #pragma unroll 4
                for (int j = 0; j < CIC; j++) {
                    const float* wa = &W1s[(24 + j) * 5];
                    const float* wb = &W1s[(48 + j) * 5];
                    float sa = b1s[24 + j];
                    sa = fmaf(wa[0], v0, sa); sa = fmaf(wa[1], v1, sa);
                    sa = fmaf(wa[2], v2, sa); sa = fmaf(wa[3], v3, sa);
                    sa = fmaf(wa[4], v4, sa);
                    float sb = b1s[48 + j];
                    sb = fmaf(wb[0], v0, sb); sb = fmaf(wb[1], v1, sb);
                    sb = fmaf(wb[2], v2, sb); sb = fmaf(wb[3], v3, sb);
                    sb = fmaf(wb[4], v4, sb);
                    Hr[j * XD + pp] = fmaxf(sa, 0.0f) * fmaxf(sb, 0.0f);
                }
            }
        }
        __syncthreads();   // Hs chunk ready

        // Phase B partial over this chunk's 24 channels
        const float* HrowR = Hs + r * HS_RSTRIDE;
        const float* W2chunk = W2s + (chunk * CIC) * 5 * COP + co0;
        #pragma unroll 1
        for (int cil = 0; cil < CIC; cil++) {
            const float* hc = HrowR + cil * XD;
            ull hp[8];
            #pragma unroll
            for (int j = 0; j < 8; j++) {
                float hv = hc[hidx[j]];
                asm("mov.b64 %0, {%1, %1};" : "=l"(hp[j]) : "f"(hv));
            }
            const float* wb = W2chunk + cil * 5 * COP;
            #pragma unroll
            for (int k = 0; k < 5; k++) {
                const ulonglong2* wv = reinterpret_cast<const ulonglong2*>(wb + k * COP);
                ulonglong2 a0 = wv[0], a1 = wv[1], a2 = wv[2], a3 = wv[3], a4 = wv[4];
                ull wp[10] = {a0.x, a0.y, a1.x, a1.y, a2.x,
                              a2.y, a3.x, a3.y, a4.x, a4.y};
                #pragma unroll
                for (int j2 = 0; j2 < P; j2++) {
                    const ull h2 = hp[j2 + k];
                    #pragma unroll
                    for (int q = 0; q < 10; q++) {
                        asm("fma.rn.f32x2 %0, %1, %2, %0;"
                            : "+l"(accp[j2 * 10 + q]) : "l"(h2), "l"(wp[q]));
                    }
                }
            }
        }
    }

    // ---- epilogue: ReLU + conv3 partial dot over this thread's 20 co ----
    float o2p[P];
    #pragma unroll
    for (int j2 = 0; j2 < P; j2++) {
        float a2 = 0.0f;
        #pragma unroll
        for (int q = 0; q < 10; q++) {
            float lo, hi;
            asm("mov.b64 {%0, %1}, %2;" : "=f"(lo), "=f"(hi) : "l"(accp[j2 * 10 + q]));
            a2 = fmaf(W3s[co0 + 2 * q],     fmaxf(lo, 0.0f), a2);
            a2 = fmaf(W3s[co0 + 2 * q + 1], fmaxf(hi, 0.0f), a2);
        }
        o2p[j2] = a2;
    }
    // combine the two co-halves (lanes s and s^1 are warp-adjacent)
    float o2t[P];
    #pragma unroll
    for (int j2 = 0; j2 < P; j2++)
        o2t[j2] = o2p[j2] + __shfl_xor_sync(0xffffffffu, o2p[j2], 1);

    if (s == 0) {
        const float* ur = us + r * XD;
        float uw[8];
        #pragma unroll
        for (int j = 0; j < 8; j++) uw[j] = ur[hidx[j]];
        const float bb3 = b3[0];
        float res[P];
        #pragma unroll
        for (int j2 = 0; j2 < P; j2++) {
            const float v0 = uw[j2], v1 = uw[j2 + 1], v2 = uw[j2 + 2],
                        v3 = uw[j2 + 3], v4 = uw[j2 + 4];
            float o1 = cfs[0];
            o1 = fmaf(cfs[1], v0, o1);  o1 = fmaf(cfs[2], v1, o1);
            o1 = fmaf(cfs[3], v2, o1);  o1 = fmaf(cfs[4], v3, o1);
            o1 = fmaf(cfs[5], v4, o1);
            o1 = fmaf(cfs[6],  v0 * v0, o1); o1 = fmaf(cfs[7],  v1 * v1, o1);
            o1 = fmaf(cfs[8],  v2 * v2, o1); o1 = fmaf(cfs[9],  v3 * v3, o1);
            o1 = fmaf(cfs[10], v4 * v4, o1);
            o1 = fmaf(cfs[11], v0 * v1, o1); o1 = fmaf(cfs[12], v1 * v2, o1);
            o1 = fmaf(cfs[13], v2 * v3, o1); o1 = fmaf(cfs[14], v3 * v4, o1);
            o1 = fmaf(cfs[15], v0 * v2, o1); o1 = fmaf(cfs[16], v1 * v3, o1);
            o1 = fmaf(cfs[17], v2 * v4, o1);
            res[j2] = o1 + o2t[j2] + bb3;
        }
        float4 vres = make_float4(res[0], res[1], res[2], res[3]);
        *reinterpret_cast<float4*>(out + base + r * XD + pbase) = vres;
    }
}

extern "C" void kernel_launch(void* const* d_in, const int* in_sizes, int n_in,
                              void* d_out, int out_size)
{
    // metadata order: t, u, coeff, W1, b1, W2, b2, W3, b3
    const float* u     = (const float*)d_in[1];
    const float* coeff = (const float*)d_in[2];
    const float* W1    = (const float*)d_in[3];
    const float* b1    = (const float*)d_in[4];
    const float* W2    = (const float*)d_in[5];
    const float* b2    = (const float*)d_in[6];
    const float* W3    = (const float*)d_in[7];
    const float* b3    = (const float*)d_in[8];
    float* out = (float*)d_out;

    const int n_rows = in_sizes[1] / XD;         // 65536
    const int grid = n_rows / ROWS;              // 8192

    cudaFuncSetAttribute(lorenz96_corr_kernel,
                         cudaFuncAttributeMaxDynamicSharedMemorySize, SMEM_BYTES);

    lorenz96_corr_kernel<<<grid, NT, SMEM_BYTES>>>(
        u, coeff, W1, b1, W2, b2, W3, b3, out);
}

// round 17
// speedup vs baseline: 1.3825x; 1.0989x over previous
#include <cuda_runtime.h>

typedef unsigned long long ull;

#define XD      40
#define ROWS    8
#define GROUPS  10           // 40 / P
#define P       4            // positions per thread
#define SPLIT   4            // co split ways
#define NT      (ROWS * GROUPS * SPLIT)   // 320 threads
#define C1      72
#define CH      48
#define CIC     24           // ci chunk size (2 chunks)
#define CO      37
#define COP     40           // padded co stride
#define HS_RSTRIDE (CIC * XD + 8)  // 968

// smem (floats): W2s 9600 | Hs 8*968=7744 | W1s 360 | b1s 72 | b2s 40 | W3s 40 | cfs 18 | us 320
#define SMEM_FLOATS (CH*5*COP + ROWS*HS_RSTRIDE + C1*5 + C1 + COP + COP + 18 + ROWS*XD)
#define SMEM_BYTES  (SMEM_FLOATS * 4)

__global__ void __launch_bounds__(NT, 2)
lorenz96_corr_kernel(const float* __restrict__ u,
                     const float* __restrict__ coeff,
                     const float* __restrict__ W1,
                     const float* __restrict__ b1,
                     const float* __restrict__ W2,
                     const float* __restrict__ b2,
                     const float* __restrict__ W3,
                     const float* __restrict__ b3,
                     float* __restrict__ out)
{
    extern __shared__ float smem[];
    float* W2s = smem;                        // [cik 240][co 40 pad]
    float* Hs  = W2s + CH * 5 * COP;          // [r][24ci][40], row stride 968
    float* W1s = Hs + ROWS * HS_RSTRIDE;
    float* b1s = W1s + C1 * 5;
    float* b2s = b1s + C1;                    // 40 (pad zeros), 8B aligned
    float* W3s = b2s + COP;                   // 40 (pad zeros)
    float* cfs = W3s + COP;
    float* us  = cfs + 18;                    // [r][40]

    const int tid = threadIdx.x;
    const long base = (long)blockIdx.x * ROWS * XD;

    // ---- cooperative loads ----
    for (int i = tid; i < CH * 5 * COP; i += NT) {
        int cik = i / COP;
        int co  = i % COP;
        W2s[i] = (co < CO) ? W2[co * (CH * 5) + cik] : 0.0f;
    }
    for (int i = tid; i < C1 * 5; i += NT) W1s[i] = W1[i];
    if (tid < C1) b1s[tid] = b1[tid];
    if (tid < COP) {
        b2s[tid] = (tid < CO) ? b2[tid] : 0.0f;
        W3s[tid] = (tid < CO) ? W3[tid] : 0.0f;
    }
    if (tid < 18) cfs[tid] = coeff[tid];
    for (int i = tid; i < ROWS * XD; i += NT) us[i] = u[base + i];
    __syncthreads();

    // ---- Phase B thread mapping: s = co-quarter, g = pos-group, r = row ----
    const int s  = tid & 3;
    const int g  = (tid >> 2) % GROUPS;
    const int r  = tid / (GROUPS * SPLIT);
    const int pbase = g * P;

    int hidx[8];
    #pragma unroll
    for (int j = 0; j < 8; j++) hidx[j] = (pbase + XD - 2 + j) % XD;

    // 4 pos x 5 strided co-pairs (pair q = s + 4j), 40 accp regs
    ull accp[P * 5];
    {
        const ull* bp = reinterpret_cast<const ull*>(b2s);
        #pragma unroll
        for (int j2 = 0; j2 < P; j2++)
            #pragma unroll
            for (int j = 0; j < 5; j++) accp[j2 * 5 + j] = bp[s + 4 * j];
    }

    // ---- two ci chunks: build Hs for 24 channels, consume, repeat ----
    #pragma unroll 1
    for (int chunk = 0; chunk < 2; chunk++) {
        __syncthreads();   // previous chunk's Hs fully consumed

        // Phase A for this chunk: 1 position-column per thread
        for (int col = tid; col < ROWS * XD; col += NT) {
            const int rr = col / XD;
            const int pp = col % XD;
            const int am2 = (pp + XD - 2) % XD, am1 = (pp + XD - 1) % XD;
            const int ap1 = (pp + 1) % XD,      ap2 = (pp + 2) % XD;
            const float* ur = us + rr * XD;
            const float v0 = ur[am2], v1 = ur[am1], v2 = ur[pp],
                        v3 = ur[ap1], v4 = ur[ap2];
            float* Hr = Hs + rr * HS_RSTRIDE;
            if (chunk == 0) {
                #pragma unroll 4
                for (int c = 0; c < CIC; c++) {
                    const float* w = &W1s[c * 5];
                    float sacc = b1s[c];
                    sacc = fmaf(w[0], v0, sacc); sacc = fmaf(w[1], v1, sacc);
                    sacc = fmaf(w[2], v2, sacc); sacc = fmaf(w[3], v3, sacc);
                    sacc = fmaf(w[4], v4, sacc);
                    Hr[c * XD + pp] = fmaxf(sacc, 0.0f);
                }
            } else {
                #pragma unroll 4
                for (int j = 0; j < CIC; j++) {
                    const float* wa = &W1s[(24 + j) * 5];
                    const float* wb = &W1s[(48 + j) * 5];
                    float sa = b1s[24 + j];
                    sa = fmaf(wa[0], v0, sa); sa = fmaf(wa[1], v1, sa);
                    sa = fmaf(wa[2], v2, sa); sa = fmaf(wa[3], v3, sa);
                    sa = fmaf(wa[4], v4, sa);
                    float sb = b1s[48 + j];
                    sb = fmaf(wb[0], v0, sb); sb = fmaf(wb[1], v1, sb);
                    sb = fmaf(wb[2], v2, sb); sb = fmaf(wb[3], v3, sb);
                    sb = fmaf(wb[4], v4, sb);
                    Hr[j * XD + pp] = fmaxf(sa, 0.0f) * fmaxf(sb, 0.0f);
                }
            }
        }
        __syncthreads();   // Hs chunk ready

        // Phase B partial over this chunk's 24 channels
        const float* HrowR = Hs + r * HS_RSTRIDE;
        const float* W2chunk = W2s + (chunk * CIC) * 5 * COP;
        #pragma unroll 1
        for (int cil = 0; cil < CIC; cil++) {
            const float* hc = HrowR + cil * XD;
            ull hp[8];
            #pragma unroll
            for (int j = 0; j < 8; j++) {
                float hv = hc[hidx[j]];
                asm("mov.b64 %0, {%1, %1};" : "=l"(hp[j]) : "f"(hv));
            }
            const float* wrowb = W2chunk + cil * 5 * COP;
            #pragma unroll
            for (int k = 0; k < 5; k++) {
                const float* wrow = wrowb + k * COP;
                ull wp[5];
                #pragma unroll
                for (int j = 0; j < 5; j++)
                    wp[j] = *reinterpret_cast<const ull*>(wrow + 2 * (s + 4 * j));
                #pragma unroll
                for (int j2 = 0; j2 < P; j2++) {
                    const ull h2 = hp[j2 + k];
                    #pragma unroll
                    for (int j = 0; j < 5; j++) {
                        asm("fma.rn.f32x2 %0, %1, %2, %0;"
                            : "+l"(accp[j2 * 5 + j]) : "l"(h2), "l"(wp[j]));
                    }
                }
            }
        }
    }

    // ---- epilogue: ReLU + conv3 partial dot over this thread's 10 co ----
    float o2t[P];
    #pragma unroll
    for (int j2 = 0; j2 < P; j2++) {
        float a2 = 0.0f;
        #pragma unroll
        for (int j = 0; j < 5; j++) {
            float lo, hi;
            asm("mov.b64 {%0, %1}, %2;" : "=f"(lo), "=f"(hi) : "l"(accp[j2 * 5 + j]));
            const int q = s + 4 * j;
            a2 = fmaf(W3s[2 * q],     fmaxf(lo, 0.0f), a2);
            a2 = fmaf(W3s[2 * q + 1], fmaxf(hi, 0.0f), a2);
        }
        // combine the four co-quarters (s lanes are 4 consecutive tids)
        a2 += __shfl_xor_sync(0xffffffffu, a2, 1);
        a2 += __shfl_xor_sync(0xffffffffu, a2, 2);
        o2t[j2] = a2;
    }

    if (s == 0) {
        const float* ur = us + r * XD;
        float uw[8];
        #pragma unroll
        for (int j = 0; j < 8; j++) uw[j] = ur[hidx[j]];
        const float bb3 = b3[0];
        float res[P];
        #pragma unroll
        for (int j2 = 0; j2 < P; j2++) {
            const float v0 = uw[j2], v1 = uw[j2 + 1], v2 = uw[j2 + 2],
                        v3 = uw[j2 + 3], v4 = uw[j2 + 4];
            float o1 = cfs[0];
            o1 = fmaf(cfs[1], v0, o1);  o1 = fmaf(cfs[2], v1, o1);
            o1 = fmaf(cfs[3], v2, o1);  o1 = fmaf(cfs[4], v3, o1);
            o1 = fmaf(cfs[5], v4, o1);
            o1 = fmaf(cfs[6],  v0 * v0, o1); o1 = fmaf(cfs[7],  v1 * v1, o1);
            o1 = fmaf(cfs[8],  v2 * v2, o1); o1 = fmaf(cfs[9],  v3 * v3, o1);
            o1 = fmaf(cfs[10], v4 * v4, o1);
            o1 = fmaf(cfs[11], v0 * v1, o1); o1 = fmaf(cfs[12], v1 * v2, o1);
            o1 = fmaf(cfs[13], v2 * v3, o1); o1 = fmaf(cfs[14], v3 * v4, o1);
            o1 = fmaf(cfs[15], v0 * v2, o1); o1 = fmaf(cfs[16], v1 * v3, o1);
            o1 = fmaf(cfs[17], v2 * v4, o1);
            res[j2] = o1 + o2t[j2] + bb3;
        }
        float4 vres = make_float4(res[0], res[1], res[2], res[3]);
        *reinterpret_cast<float4*>(out + base + r * XD + pbase) = vres;
    }
}

extern "C" void kernel_launch(void* const* d_in, const int* in_sizes, int n_in,
                              void* d_out, int out_size)
{
    // metadata order: t, u, coeff, W1, b1, W2, b2, W3, b3
    const float* u     = (const float*)d_in[1];
    const float* coeff = (const float*)d_in[2];
    const float* W1    = (const float*)d_in[3];
    const float* b1    = (const float*)d_in[4];
    const float* W2    = (const float*)d_in[5];
    const float* b2    = (const float*)d_in[6];
    const float* W3    = (const float*)d_in[7];
    const float* b3    = (const float*)d_in[8];
    float* out = (float*)d_out;

    const int n_rows = in_sizes[1] / XD;         // 65536
    const int grid = n_rows / ROWS;              // 8192

    cudaFuncSetAttribute(lorenz96_corr_kernel,
                         cudaFuncAttributeMaxDynamicSharedMemorySize, SMEM_BYTES);

    lorenz96_corr_kernel<<<grid, NT, SMEM_BYTES>>>(
        u, coeff, W1, b1, W2, b2, W3, b3, out);
}